// round 1
// baseline (speedup 1.0000x reference)
#include <cuda_runtime.h>
#include <math.h>

// Problem constants
#define BB 4
#define LL 64
#define SS 64
#define NN 768
#define DD 64
#define HH 8
#define DK 8
#define CING 192   // (ORDER*SUP+1)*D

#define PAD 68     // smem row pad (keeps float4 alignment, spreads banks)

// ---------------- scratch (__device__ globals; no allocations allowed) ----------------
__device__ float g_At[NN * NN];                 // A^T  (At[n][v] = a[v][n])
__device__ float g_A2[NN * NN];                 // At @ At
__device__ float g_K1[BB * SS * NN * DD];       // 1-hop diffused keys
__device__ float g_K2[BB * SS * NN * DD];       // 2-hop diffused keys
__device__ float g_V1[BB * SS * NN * DD];
__device__ float g_V2[BB * SS * NN * DD];
__device__ float g_WkG1[DD * CING];             // Wk @ Wg1   [64 x 192]
__device__ float g_WvG2[DD * CING];
__device__ float g_bk2[DD];                     // Wk@bg1 + bk
__device__ float g_bv2[DD];

// ---------------- prep: transpose support ----------------
__global__ void transpose_kernel(const float* __restrict__ a) {
    int idx = blockIdx.x * 256 + threadIdx.x;
    if (idx < NN * NN) {
        int n = idx / NN;
        int v = idx - n * NN;
        g_At[idx] = a[v * NN + n];
    }
}

// ---------------- prep: fold MLP weight into K/V projections ----------------
__global__ void prep_w_kernel(const float* __restrict__ Wk, const float* __restrict__ bk,
                              const float* __restrict__ Wg1, const float* __restrict__ bg1,
                              const float* __restrict__ Wv, const float* __restrict__ bv,
                              const float* __restrict__ Wg2, const float* __restrict__ bg2) {
    const float* W1 = blockIdx.x ? Wv : Wk;
    const float* Wg = blockIdx.x ? Wg2 : Wg1;
    const float* bg = blockIdx.x ? bg2 : bg1;
    const float* bb = blockIdx.x ? bv : bk;
    float* WG = blockIdx.x ? g_WvG2 : g_WkG1;
    float* b2 = blockIdx.x ? g_bv2 : g_bk2;

    __shared__ float sW[DD * DD];
    for (int i = threadIdx.x; i < DD * DD; i += 256) sW[i] = W1[i];
    __syncthreads();

    for (int idx = threadIdx.x; idx < DD * CING; idx += 256) {
        int e = idx / CING;
        int c = idx - e * CING;
        float s = 0.f;
        #pragma unroll 8
        for (int o = 0; o < DD; ++o) s += sW[e * DD + o] * Wg[o * CING + c];
        WG[idx] = s;
    }
    if (threadIdx.x < DD) {
        float s = 0.f;
        for (int o = 0; o < DD; ++o) s += sW[threadIdx.x * DD + o] * bg[o];
        b2[threadIdx.x] = s + bb[threadIdx.x];
    }
}

// ---------------- tiled 64x64x64-step SGEMM helpers ----------------
__device__ __forceinline__ void mm16(const float* __restrict__ sXt, const float* __restrict__ sWt,
                                     int tx, int ty, float acc[4][4]) {
    #pragma unroll 8
    for (int d = 0; d < 64; ++d) {
        float4 xv = *(const float4*)(sXt + d * PAD + ty * 4);
        float4 wv = *(const float4*)(sWt + d * PAD + tx * 4);
        float xs[4] = {xv.x, xv.y, xv.z, xv.w};
        float ws[4] = {wv.x, wv.y, wv.z, wv.w};
        #pragma unroll
        for (int i = 0; i < 4; ++i)
            #pragma unroll
            for (int j = 0; j < 4; ++j)
                acc[i][j] += xs[i] * ws[j];
    }
}

// stage a 64x64 fp32 tile (row-major src, given row stride) TRANSPOSED into dst[d][r] (PAD stride)
__device__ __forceinline__ void stage_xt(const float* __restrict__ src, long rowstride,
                                         float* __restrict__ dst, int tid) {
    #pragma unroll
    for (int it = 0; it < 4; ++it) {
        int idx = tid + it * 256;
        int r = idx >> 4;
        int c4 = (idx & 15) << 2;
        float4 f = *(const float4*)(src + (long)r * rowstride + c4);
        dst[(c4 + 0) * PAD + r] = f.x;
        dst[(c4 + 1) * PAD + r] = f.y;
        dst[(c4 + 2) * PAD + r] = f.z;
        dst[(c4 + 3) * PAD + r] = f.w;
    }
}

// ---------------- A2 = At @ At  (768x768x768) ----------------
__global__ __launch_bounds__(256) void gemm_sq_kernel() {
    __shared__ float MsT[64 * PAD];
    __shared__ float Xs[64 * PAD];
    const int tid = threadIdx.x;
    const int tx = tid & 15, ty = tid >> 4;
    const int n0 = blockIdx.x * 64;
    const int d0 = blockIdx.y * 64;

    float acc[4][4] = {};
    for (int kt = 0; kt < 12; ++kt) {
        #pragma unroll
        for (int it = 0; it < 4; ++it) {
            int idx = tid + it * 256;
            int r = idx >> 4;
            int c4 = (idx & 15) << 2;
            float4 m = *(const float4*)(g_At + (long)(n0 + r) * NN + kt * 64 + c4);
            MsT[(c4 + 0) * PAD + r] = m.x;
            MsT[(c4 + 1) * PAD + r] = m.y;
            MsT[(c4 + 2) * PAD + r] = m.z;
            MsT[(c4 + 3) * PAD + r] = m.w;
            float4 x = *(const float4*)(g_At + (long)(kt * 64 + r) * NN + d0 + c4);
            *(float4*)&Xs[r * PAD + c4] = x;
        }
        __syncthreads();
        #pragma unroll 8
        for (int k = 0; k < 64; ++k) {
            float4 mm = *(const float4*)&MsT[k * PAD + ty * 4];
            float4 xx = *(const float4*)&Xs[k * PAD + tx * 4];
            float ms[4] = {mm.x, mm.y, mm.z, mm.w};
            float xs[4] = {xx.x, xx.y, xx.z, xx.w};
            #pragma unroll
            for (int i = 0; i < 4; ++i)
                #pragma unroll
                for (int j = 0; j < 4; ++j)
                    acc[i][j] += ms[i] * xs[j];
        }
        __syncthreads();
    }
    #pragma unroll
    for (int i = 0; i < 4; ++i) {
        float4 o = make_float4(acc[i][0], acc[i][1], acc[i][2], acc[i][3]);
        *(float4*)(g_A2 + (long)(n0 + 4 * ty + i) * NN + d0 + 4 * tx) = o;
    }
}

// ---------------- diffusion GEMMs: C[bs] = M @ X[bs]  (768x64, K=768) ----------------
// var: 0 -> (At, keys)->K1 ; 1 -> (A2, keys)->K2 ; 2 -> (At, values)->V1 ; 3 -> (A2, values)->V2
__global__ __launch_bounds__(256) void gemm_diff_kernel(const float* __restrict__ keys,
                                                        const float* __restrict__ values) {
    __shared__ float MsT[64 * PAD];
    __shared__ float Xs[64 * PAD];
    const int tid = threadIdx.x;
    const int tx = tid & 15, ty = tid >> 4;
    const int n0 = blockIdx.x * 64;
    const int bs = blockIdx.y;
    const int var = blockIdx.z;

    const float* M = (var & 1) ? g_A2 : g_At;
    const float* X = ((var < 2) ? keys : values) + (long)bs * NN * DD;
    float* C = (var == 0 ? g_K1 : var == 1 ? g_K2 : var == 2 ? g_V1 : g_V2) + (long)bs * NN * DD;

    float acc[4][4] = {};
    for (int kt = 0; kt < 12; ++kt) {
        #pragma unroll
        for (int it = 0; it < 4; ++it) {
            int idx = tid + it * 256;
            int r = idx >> 4;
            int c4 = (idx & 15) << 2;
            float4 m = *(const float4*)(M + (long)(n0 + r) * NN + kt * 64 + c4);
            MsT[(c4 + 0) * PAD + r] = m.x;
            MsT[(c4 + 1) * PAD + r] = m.y;
            MsT[(c4 + 2) * PAD + r] = m.z;
            MsT[(c4 + 3) * PAD + r] = m.w;
            float4 x = *(const float4*)(X + (long)(kt * 64 + r) * DD + c4);
            *(float4*)&Xs[r * PAD + c4] = x;
        }
        __syncthreads();
        #pragma unroll 8
        for (int k = 0; k < 64; ++k) {
            float4 mm = *(const float4*)&MsT[k * PAD + ty * 4];
            float4 xx = *(const float4*)&Xs[k * PAD + tx * 4];
            float ms[4] = {mm.x, mm.y, mm.z, mm.w};
            float xs[4] = {xx.x, xx.y, xx.z, xx.w};
            #pragma unroll
            for (int i = 0; i < 4; ++i)
                #pragma unroll
                for (int j = 0; j < 4; ++j)
                    acc[i][j] += ms[i] * xs[j];
        }
        __syncthreads();
    }
    #pragma unroll
    for (int i = 0; i < 4; ++i) {
        float4 o = make_float4(acc[i][0], acc[i][1], acc[i][2], acc[i][3]);
        *(float4*)(C + (long)(n0 + 4 * ty + i) * DD + 4 * tx) = o;
    }
}

// ---------------- fused projections + per-node attention + output projection ----------------
// grid (N, B), 256 threads. One block handles all L=S=64 timesteps for one (b, n).
__global__ __launch_bounds__(256) void attn_kernel(const float* __restrict__ queries,
                                                   const float* __restrict__ keys,
                                                   const float* __restrict__ values,
                                                   const float* __restrict__ Wq,
                                                   const float* __restrict__ bq,
                                                   const float* __restrict__ Wo,
                                                   const float* __restrict__ bo,
                                                   float* __restrict__ out) {
    extern __shared__ float sm[];
    float* sXt = sm;                 // 64*PAD staging (transposed), later reused as attn-out^T
    float* sWt = sm + 64 * PAD;      // 64*PAD weight staging (transposed)
    float* sq = sm + 2 * 64 * PAD;   // projected q [l][e]
    float* sk = sm + 3 * 64 * PAD;   // projected k [s][e]
    float* sv = sm + 4 * 64 * PAD;   // projected v [s][e]

    const int n = blockIdx.x;
    const int b = blockIdx.y;
    const int tid = threadIdx.x;
    const int tx = tid & 15, ty = tid >> 4;
    const long rowstride = (long)NN * DD;
    const long base = ((long)b * 64 * NN + n) * DD;

    // ---- Q projection: sq[l][e] = (Q[l] . Wq[e]) + bq[e], scaled by 1/sqrt(DK) ----
    {
        stage_xt(queries + base, rowstride, sXt, tid);
        stage_xt(Wq, DD, sWt, tid);
        __syncthreads();
        float acc[4][4] = {};
        mm16(sXt, sWt, tx, ty, acc);
        __syncthreads();
        const float sc = 0.35355339059327373f;  // 1/sqrt(8)
        #pragma unroll
        for (int i = 0; i < 4; ++i)
            #pragma unroll
            for (int j = 0; j < 4; ++j)
                sq[(4 * ty + i) * PAD + 4 * tx + j] = (acc[i][j] + bq[4 * tx + j]) * sc;
    }

    // ---- K projection over 3 chunks (keys, K1, K2) with folded weight WkG1 ----
    {
        float acc[4][4] = {};
        #pragma unroll
        for (int ch = 0; ch < 3; ++ch) {
            const float* X = (ch == 0) ? keys + base : (ch == 1) ? g_K1 + base : g_K2 + base;
            stage_xt(X, rowstride, sXt, tid);
            stage_xt(g_WkG1 + ch * 64, CING, sWt, tid);
            __syncthreads();
            mm16(sXt, sWt, tx, ty, acc);
            __syncthreads();
        }
        #pragma unroll
        for (int i = 0; i < 4; ++i)
            #pragma unroll
            for (int j = 0; j < 4; ++j)
                sk[(4 * ty + i) * PAD + 4 * tx + j] = acc[i][j] + g_bk2[4 * tx + j];
    }

    // ---- V projection over 3 chunks (values, V1, V2) with folded weight WvG2 ----
    {
        float acc[4][4] = {};
        #pragma unroll
        for (int ch = 0; ch < 3; ++ch) {
            const float* X = (ch == 0) ? values + base : (ch == 1) ? g_V1 + base : g_V2 + base;
            stage_xt(X, rowstride, sXt, tid);
            stage_xt(g_WvG2 + ch * 64, CING, sWt, tid);
            __syncthreads();
            mm16(sXt, sWt, tx, ty, acc);
            __syncthreads();
        }
        #pragma unroll
        for (int i = 0; i < 4; ++i)
            #pragma unroll
            for (int j = 0; j < 4; ++j)
                sv[(4 * ty + i) * PAD + 4 * tx + j] = acc[i][j] + g_bv2[4 * tx + j];
    }

    // stage Wo^T for the final projection (sWt free after last sync above)
    stage_xt(Wo, DD, sWt, tid);
    __syncthreads();  // sq/sk/sv/sWt all visible

    // ---- attention: warp w handles head h=w; lane handles query rows (lane, lane+32) ----
    {
        const int h = tid >> 5;
        const int lane = tid & 31;
        float qa[DK], qb[DK], aa[DK] = {}, ab[DK] = {};
        #pragma unroll
        for (int i = 0; i < DK; ++i) {
            qa[i] = sq[lane * PAD + h * DK + i];
            qb[i] = sq[(lane + 32) * PAD + h * DK + i];
        }
        float ma = -1e30f, mb = -1e30f, sa = 0.f, sb = 0.f;
        for (int s = 0; s < SS; ++s) {
            float da = 0.f, db = 0.f;
            #pragma unroll
            for (int i = 0; i < DK; ++i) {
                float kk = sk[s * PAD + h * DK + i];
                da += qa[i] * kk;
                db += qb[i] * kk;
            }
            float mna = fmaxf(ma, da), mnb = fmaxf(mb, db);
            float ca = __expf(ma - mna), pa = __expf(da - mna);
            float cb = __expf(mb - mnb), pb = __expf(db - mnb);
            sa = sa * ca + pa;
            sb = sb * cb + pb;
            ma = mna; mb = mnb;
            #pragma unroll
            for (int i = 0; i < DK; ++i) {
                float vv = sv[s * PAD + h * DK + i];
                aa[i] = aa[i] * ca + pa * vv;
                ab[i] = ab[i] * cb + pb * vv;
            }
        }
        float ra = 1.f / sa, rb = 1.f / sb;
        #pragma unroll
        for (int i = 0; i < DK; ++i) {
            sXt[(h * DK + i) * PAD + lane] = aa[i] * ra;        // attn-out^T [d][l]
            sXt[(h * DK + i) * PAD + lane + 32] = ab[i] * rb;
        }
    }
    __syncthreads();

    // ---- output projection: out[l][e] = sum_d attnout[l][d] * Wo[e][d] + bo[e] ----
    {
        float acc[4][4] = {};
        mm16(sXt, sWt, tx, ty, acc);
        #pragma unroll
        for (int i = 0; i < 4; ++i) {
            int l = 4 * ty + i;
            float4 o = make_float4(acc[i][0] + bo[4 * tx + 0],
                                   acc[i][1] + bo[4 * tx + 1],
                                   acc[i][2] + bo[4 * tx + 2],
                                   acc[i][3] + bo[4 * tx + 3]);
            *(float4*)(out + ((long)(b * LL + l) * NN + n) * DD + 4 * tx) = o;
        }
    }
}

// ---------------- launch ----------------
extern "C" void kernel_launch(void* const* d_in, const int* in_sizes, int n_in,
                              void* d_out, int out_size) {
    const float* queries = (const float*)d_in[0];
    const float* keys    = (const float*)d_in[1];
    const float* values  = (const float*)d_in[2];
    const float* support = (const float*)d_in[3];
    const float* Wq = (const float*)d_in[4];
    const float* bq = (const float*)d_in[5];
    const float* Wk = (const float*)d_in[6];
    const float* bk = (const float*)d_in[7];
    const float* Wv = (const float*)d_in[8];
    const float* bv = (const float*)d_in[9];
    const float* Wo = (const float*)d_in[10];
    const float* bo = (const float*)d_in[11];
    const float* Wg1 = (const float*)d_in[12];
    const float* bg1 = (const float*)d_in[13];
    const float* Wg2 = (const float*)d_in[14];
    const float* bg2 = (const float*)d_in[15];
    float* out = (float*)d_out;

    transpose_kernel<<<(NN * NN + 255) / 256, 256>>>(support);
    prep_w_kernel<<<2, 256>>>(Wk, bk, Wg1, bg1, Wv, bv, Wg2, bg2);
    gemm_sq_kernel<<<dim3(12, 12), 256>>>();
    gemm_diff_kernel<<<dim3(12, 256, 4), 256>>>(keys, values);

    const int smem = 5 * 64 * PAD * (int)sizeof(float);  // 87,040 B
    cudaFuncSetAttribute(attn_kernel, cudaFuncAttributeMaxDynamicSharedMemorySize, smem);
    attn_kernel<<<dim3(NN, BB), 256, smem>>>(queries, keys, values, Wq, bq, Wo, bo, out);
}

// round 4
// speedup vs baseline: 2.1582x; 2.1582x over previous
#include <cuda_runtime.h>
#include <cuda_bf16.h>
#include <cstdint>
#include <math.h>

// Problem constants
#define BB 4
#define LL 64
#define SS 64
#define NN 768
#define DD 64
#define HH 8
#define DK 8
#define CING 192   // (ORDER*SUP+1)*D
#define JJ 16384   // B*S*D = 256*64

#define PAD 68     // smem row pad for fp32 SIMT tiles

// ---------------- scratch (__device__ globals; no allocations allowed) ----------------
__device__ float g_At[NN * NN];                 // A^T  (At[n][v] = a[v][n])
__device__ float g_A2[NN * NN];                 // At @ At
__device__ float g_KtT[JJ * NN];                // keys transposed: [j = bs*64+d][v]
__device__ float g_VtT[JJ * NN];
__device__ float g_K1[NN * JJ];                 // 1-hop diffused keys  [n][j]
__device__ float g_K2[NN * JJ];                 // 2-hop
__device__ float g_V1[NN * JJ];
__device__ float g_V2[NN * JJ];
__device__ float g_WkG1[DD * CING];             // Wk @ Wg1   [64 x 192]
__device__ float g_WvG2[DD * CING];
__device__ float g_bk2[DD];                     // Wk@bg1 + bk
__device__ float g_bv2[DD];

// ================= PTX helpers (vanilla compute_103 features only) =================
__device__ __forceinline__ uint32_t smem_u32_of(const void* p) {
    uint32_t a;
    asm("{ .reg .u64 t; cvta.to.shared.u64 t, %1; cvt.u32.u64 %0, t; }" : "=r"(a) : "l"(p));
    return a;
}
__device__ __forceinline__ void ldm_x4(uint32_t& r0, uint32_t& r1, uint32_t& r2, uint32_t& r3,
                                       uint32_t addr) {
    asm volatile("ldmatrix.sync.aligned.m8n8.x4.shared.b16 {%0,%1,%2,%3}, [%4];"
                 : "=r"(r0), "=r"(r1), "=r"(r2), "=r"(r3) : "r"(addr));
}
__device__ __forceinline__ void mma_bf16(float* c, const uint32_t* a, const uint32_t* b) {
    asm volatile("mma.sync.aligned.m16n8k16.row.col.f32.bf16.bf16.f32 "
                 "{%0,%1,%2,%3}, {%4,%5,%6,%7}, {%8,%9}, {%0,%1,%2,%3};"
                 : "+f"(c[0]), "+f"(c[1]), "+f"(c[2]), "+f"(c[3])
                 : "r"(a[0]), "r"(a[1]), "r"(a[2]), "r"(a[3]), "r"(b[0]), "r"(b[1]));
}

// ---------------- prep: transpose support ----------------
__global__ void transpose_kernel(const float* __restrict__ a) {
    int idx = blockIdx.x * 256 + threadIdx.x;
    if (idx < NN * NN) {
        int n = idx / NN;
        int v = idx - n * NN;
        g_At[idx] = a[v * NN + n];
    }
}

// ---------------- prep: transpose keys/values per-(b,s): [n][d] -> KtT[(bs*64+d)][n] ----------------
__global__ __launch_bounds__(256) void pack_kernel(const float* __restrict__ keys,
                                                   const float* __restrict__ values) {
    __shared__ float tk[32][33];
    __shared__ float tv[32][33];
    const int tx = threadIdx.x & 31, ty = threadIdx.x >> 5;  // 32 x 8
    const int n0 = blockIdx.x * 32, d0 = blockIdx.y * 32;
    const int bs = blockIdx.z;
    const long inbase = (long)bs * NN * DD;
    #pragma unroll
    for (int j = 0; j < 32; j += 8) {
        tk[ty + j][tx] = keys[inbase + (long)(n0 + ty + j) * DD + d0 + tx];
        tv[ty + j][tx] = values[inbase + (long)(n0 + ty + j) * DD + d0 + tx];
    }
    __syncthreads();
    #pragma unroll
    for (int j = 0; j < 32; j += 8) {
        long o = (long)(bs * 64 + d0 + ty + j) * NN + n0 + tx;
        g_KtT[o] = tk[tx][ty + j];
        g_VtT[o] = tv[tx][ty + j];
    }
}

// ---------------- prep: fold MLP weight into K/V projections ----------------
__global__ void prep_w_kernel(const float* __restrict__ Wk, const float* __restrict__ bk,
                              const float* __restrict__ Wg1, const float* __restrict__ bg1,
                              const float* __restrict__ Wv, const float* __restrict__ bv,
                              const float* __restrict__ Wg2, const float* __restrict__ bg2) {
    const float* W1 = blockIdx.x ? Wv : Wk;
    const float* Wg = blockIdx.x ? Wg2 : Wg1;
    const float* bg = blockIdx.x ? bg2 : bg1;
    const float* bb = blockIdx.x ? bv : bk;
    float* WG = blockIdx.x ? g_WvG2 : g_WkG1;
    float* b2 = blockIdx.x ? g_bv2 : g_bk2;

    __shared__ float sW[DD * DD];
    for (int i = threadIdx.x; i < DD * DD; i += 256) sW[i] = W1[i];
    __syncthreads();

    for (int idx = threadIdx.x; idx < DD * CING; idx += 256) {
        int e = idx / CING;
        int c = idx - e * CING;
        float s = 0.f;
        #pragma unroll 8
        for (int o = 0; o < DD; ++o) s += sW[e * DD + o] * Wg[o * CING + c];
        WG[idx] = s;
    }
    if (threadIdx.x < DD) {
        float s = 0.f;
        for (int o = 0; o < DD; ++o) s += sW[threadIdx.x * DD + o] * bg[o];
        b2[threadIdx.x] = s + bb[threadIdx.x];
    }
}

// =========================================================================
// mma.sync bf16x3 GEMM:  C[m, j] = sum_k A[m,k] * B[j,k]   (fp32 in/out)
// A: lda=768.  B: ldb=768 (row j contiguous over k).  CTA tile: 128(M) x 128(N), Kc=64.
// 8 warps in 2(M) x 4(N); warp tile 64 x 32 via m16n8k16 atoms (4 m-atoms x 4 n-atoms).
// mode 0: A2 = At @ support   (grid.x = 6*6,   C=g_A2,  ldc=768,  B=support)
// mode 1: diffusion           (grid.x = 6*128, grid.y = var 0..3, ldc=16384)
// blockIdx.x = ntile*6 + mtile so CTAs sharing a B strip are schedule-adjacent (L2 reuse).
// =========================================================================
#define KROW 72                  // bf16 elements per smem row (64 + 8 pad)
#define TILE_BYTES 18432         // 128 * 72 * 2
#define AH_OFF 0
#define AL_OFF 18432
#define BH_OFF 36864
#define BL_OFF 55296
#define STAGE_BYTES 73728
#define GEMM_SMEM (2 * STAGE_BYTES)

__global__ __launch_bounds__(256, 1) void gemm_mma_kernel(const float* __restrict__ Bext, int mode) {
    extern __shared__ char smem[];
    const uint32_t smem_b = smem_u32_of(smem);
    const int tid = threadIdx.x;
    const int wid = tid >> 5, lane = tid & 31;
    const int warp_m = wid & 1;        // 0..1  -> 64-row slab
    const int warp_n = wid >> 1;       // 0..3  -> 32-col slab

    const int mtile = blockIdx.x % 6;
    const int ntile = blockIdx.x / 6;
    const int m0 = mtile * 128;
    const int j0 = ntile * 128;

    const float* Ap;
    const float* Bp;
    float* Cp;
    long ldc;
    if (mode == 0) { Ap = g_At; Bp = Bext; Cp = g_A2; ldc = NN; }
    else {
        int var = blockIdx.y;
        Ap = (var & 1) ? g_A2 : g_At;
        Bp = (var < 2) ? g_KtT : g_VtT;
        Cp = (var == 0) ? g_K1 : (var == 1) ? g_K2 : (var == 2) ? g_V1 : g_V2;
        ldc = JJ;
    }

    // staging registers (fp32, converted to hi/lo bf16 after the MMA phase)
    float4 ra[8], rb[8];

    // per-thread LDG/STS geometry: idx = tid + i*256 -> row = idx>>4 (0..127), col4 = (idx&15)*4
    #define LDG_STAGE(kt)                                                            \
        {                                                                            \
            const float* Asrc = Ap + (long)m0 * NN + (kt) * 64;                      \
            const float* Bsrc = Bp + (long)j0 * NN + (kt) * 64;                      \
            _Pragma("unroll")                                                        \
            for (int i = 0; i < 8; ++i) {                                            \
                int idx = tid + (i << 8);                                            \
                int r = idx >> 4, c4 = (idx & 15) << 2;                              \
                ra[i] = *(const float4*)(Asrc + (long)r * NN + c4);                  \
                rb[i] = *(const float4*)(Bsrc + (long)r * NN + c4);                  \
            }                                                                        \
        }

    #define STS_STAGE(buf)                                                           \
        {                                                                            \
            char* sb = smem + (buf) * STAGE_BYTES;                                   \
            _Pragma("unroll")                                                        \
            for (int i = 0; i < 8; ++i) {                                            \
                int idx = tid + (i << 8);                                            \
                int r = idx >> 4, c4 = (idx & 15) << 2;                              \
                int off = r * (KROW * 2) + c4 * 2;                                   \
                float4 f = ra[i];                                                    \
                __nv_bfloat162 h01 = __floats2bfloat162_rn(f.x, f.y);                \
                __nv_bfloat162 h23 = __floats2bfloat162_rn(f.z, f.w);                \
                float2 g01 = __bfloat1622float2(h01);                                \
                float2 g23 = __bfloat1622float2(h23);                                \
                __nv_bfloat162 l01 = __floats2bfloat162_rn(f.x - g01.x, f.y - g01.y);\
                __nv_bfloat162 l23 = __floats2bfloat162_rn(f.z - g23.x, f.w - g23.y);\
                *(uint2*)(sb + AH_OFF + off) = make_uint2(*(uint32_t*)&h01, *(uint32_t*)&h23); \
                *(uint2*)(sb + AL_OFF + off) = make_uint2(*(uint32_t*)&l01, *(uint32_t*)&l23); \
                f = rb[i];                                                           \
                h01 = __floats2bfloat162_rn(f.x, f.y);                               \
                h23 = __floats2bfloat162_rn(f.z, f.w);                               \
                g01 = __bfloat1622float2(h01);                                       \
                g23 = __bfloat1622float2(h23);                                       \
                l01 = __floats2bfloat162_rn(f.x - g01.x, f.y - g01.y);               \
                l23 = __floats2bfloat162_rn(f.z - g23.x, f.w - g23.y);               \
                *(uint2*)(sb + BH_OFF + off) = make_uint2(*(uint32_t*)&h01, *(uint32_t*)&h23); \
                *(uint2*)(sb + BL_OFF + off) = make_uint2(*(uint32_t*)&l01, *(uint32_t*)&l23); \
            }                                                                        \
        }

    float acc[4][4][4] = {};   // [m-atom][n-atom][4]

    // ldmatrix address templates
    const int a_r = lane & 15;                 // row within 16
    const int a_c = (lane >> 4) << 3;          // 0 or 8 (k offset)
    const int b_m = lane >> 3;                 // matrix index 0..3
    const int b_n = (lane & 7) + ((b_m >> 1) << 3);   // row (n) within 16
    const int b_k = (b_m & 1) << 3;            // 0 or 8 (k offset)

    const uint32_t a_base = (uint32_t)((warp_m * 64 + a_r) * (KROW * 2) + a_c * 2);
    const uint32_t b_base = (uint32_t)((warp_n * 32 + b_n) * (KROW * 2) + b_k * 2);

    // prologue
    LDG_STAGE(0);
    STS_STAGE(0);
    __syncthreads();

    for (int kt = 0; kt < 12; ++kt) {
        if (kt < 11) LDG_STAGE(kt + 1);

        const uint32_t sbase = smem_b + (kt & 1) * STAGE_BYTES;
        #pragma unroll
        for (int kc = 0; kc < 4; ++kc) {
            const uint32_t kO = kc * 32;  // 16 bf16 = 32 bytes
            uint32_t ah[4][4], al[4][4], bh[4][2], bl[4][2];
            #pragma unroll
            for (int mi = 0; mi < 4; ++mi) {
                uint32_t ad = sbase + a_base + mi * (16 * KROW * 2) + kO;
                ldm_x4(ah[mi][0], ah[mi][1], ah[mi][2], ah[mi][3], ad + AH_OFF);
                ldm_x4(al[mi][0], al[mi][1], al[mi][2], al[mi][3], ad + AL_OFF);
            }
            #pragma unroll
            for (int p = 0; p < 2; ++p) {
                uint32_t bd = sbase + b_base + p * (16 * KROW * 2) + kO;
                ldm_x4(bh[2 * p][0], bh[2 * p][1], bh[2 * p + 1][0], bh[2 * p + 1][1], bd + BH_OFF);
                ldm_x4(bl[2 * p][0], bl[2 * p][1], bl[2 * p + 1][0], bl[2 * p + 1][1], bd + BL_OFF);
            }
            #pragma unroll
            for (int mi = 0; mi < 4; ++mi)
                #pragma unroll
                for (int nj = 0; nj < 4; ++nj) {
                    mma_bf16(acc[mi][nj], ah[mi], bh[nj]);
                    mma_bf16(acc[mi][nj], ah[mi], bl[nj]);
                    mma_bf16(acc[mi][nj], al[mi], bh[nj]);
                }
        }

        if (kt < 11) STS_STAGE((kt + 1) & 1);
        __syncthreads();
    }

    // epilogue: fp32 accumulators -> global
    {
        const int g = lane >> 2, t = lane & 3;
        #pragma unroll
        for (int mi = 0; mi < 4; ++mi) {
            const int row0 = m0 + warp_m * 64 + mi * 16 + g;
            #pragma unroll
            for (int nj = 0; nj < 4; ++nj) {
                const int col = j0 + warp_n * 32 + nj * 8 + t * 2;
                *(float2*)(Cp + (long)row0 * ldc + col) =
                    make_float2(acc[mi][nj][0], acc[mi][nj][1]);
                *(float2*)(Cp + (long)(row0 + 8) * ldc + col) =
                    make_float2(acc[mi][nj][2], acc[mi][nj][3]);
            }
        }
    }
    #undef LDG_STAGE
    #undef STS_STAGE
}

// ---------------- tiled 64x64x64-step SGEMM helpers (attn kernel) ----------------
__device__ __forceinline__ void mm16(const float* __restrict__ sXt, const float* __restrict__ sWt,
                                     int tx, int ty, float acc[4][4]) {
    #pragma unroll 8
    for (int d = 0; d < 64; ++d) {
        float4 xv = *(const float4*)(sXt + d * PAD + ty * 4);
        float4 wv = *(const float4*)(sWt + d * PAD + tx * 4);
        float xs[4] = {xv.x, xv.y, xv.z, xv.w};
        float ws[4] = {wv.x, wv.y, wv.z, wv.w};
        #pragma unroll
        for (int i = 0; i < 4; ++i)
            #pragma unroll
            for (int j = 0; j < 4; ++j)
                acc[i][j] += xs[i] * ws[j];
    }
}

__device__ __forceinline__ void stage_xt(const float* __restrict__ src, long rowstride,
                                         float* __restrict__ dst, int tid) {
    #pragma unroll
    for (int it = 0; it < 4; ++it) {
        int idx = tid + it * 256;
        int r = idx >> 4;
        int c4 = (idx & 15) << 2;
        float4 f = *(const float4*)(src + (long)r * rowstride + c4);
        dst[(c4 + 0) * PAD + r] = f.x;
        dst[(c4 + 1) * PAD + r] = f.y;
        dst[(c4 + 2) * PAD + r] = f.z;
        dst[(c4 + 3) * PAD + r] = f.w;
    }
}

// ---------------- fused projections + per-node attention + output projection ----------------
__global__ __launch_bounds__(256) void attn_kernel(const float* __restrict__ queries,
                                                   const float* __restrict__ keys,
                                                   const float* __restrict__ values,
                                                   const float* __restrict__ Wq,
                                                   const float* __restrict__ bq,
                                                   const float* __restrict__ Wo,
                                                   const float* __restrict__ bo,
                                                   float* __restrict__ out) {
    extern __shared__ float sm[];
    float* sXt = sm;
    float* sWt = sm + 64 * PAD;
    float* sq = sm + 2 * 64 * PAD;
    float* sk = sm + 3 * 64 * PAD;
    float* sv = sm + 4 * 64 * PAD;

    const int n = blockIdx.x;
    const int b = blockIdx.y;
    const int tid = threadIdx.x;
    const int tx = tid & 15, ty = tid >> 4;
    const long rowstride = (long)NN * DD;
    const long base = ((long)b * 64 * NN + n) * DD;
    const long dbase = (long)n * JJ + (long)b * 4096;   // diffused scratch: [n][b*4096 + s*64 + d]

    // ---- Q projection ----
    {
        stage_xt(queries + base, rowstride, sXt, tid);
        stage_xt(Wq, DD, sWt, tid);
        __syncthreads();
        float acc[4][4] = {};
        mm16(sXt, sWt, tx, ty, acc);
        __syncthreads();
        const float sc = 0.35355339059327373f;  // 1/sqrt(8)
        #pragma unroll
        for (int i = 0; i < 4; ++i)
            #pragma unroll
            for (int j = 0; j < 4; ++j)
                sq[(4 * ty + i) * PAD + 4 * tx + j] = (acc[i][j] + bq[4 * tx + j]) * sc;
    }

    // ---- K projection over chunks (keys, K1, K2) with folded weight WkG1 ----
    {
        float acc[4][4] = {};
        #pragma unroll
        for (int ch = 0; ch < 3; ++ch) {
            const float* X = (ch == 0) ? keys + base : (ch == 1) ? g_K1 + dbase : g_K2 + dbase;
            long rs = (ch == 0) ? rowstride : 64;
            stage_xt(X, rs, sXt, tid);
            stage_xt(g_WkG1 + ch * 64, CING, sWt, tid);
            __syncthreads();
            mm16(sXt, sWt, tx, ty, acc);
            __syncthreads();
        }
        #pragma unroll
        for (int i = 0; i < 4; ++i)
            #pragma unroll
            for (int j = 0; j < 4; ++j)
                sk[(4 * ty + i) * PAD + 4 * tx + j] = acc[i][j] + g_bk2[4 * tx + j];
    }

    // ---- V projection ----
    {
        float acc[4][4] = {};
        #pragma unroll
        for (int ch = 0; ch < 3; ++ch) {
            const float* X = (ch == 0) ? values + base : (ch == 1) ? g_V1 + dbase : g_V2 + dbase;
            long rs = (ch == 0) ? rowstride : 64;
            stage_xt(X, rs, sXt, tid);
            stage_xt(g_WvG2 + ch * 64, CING, sWt, tid);
            __syncthreads();
            mm16(sXt, sWt, tx, ty, acc);
            __syncthreads();
        }
        #pragma unroll
        for (int i = 0; i < 4; ++i)
            #pragma unroll
            for (int j = 0; j < 4; ++j)
                sv[(4 * ty + i) * PAD + 4 * tx + j] = acc[i][j] + g_bv2[4 * tx + j];
    }

    stage_xt(Wo, DD, sWt, tid);
    __syncthreads();

    // ---- attention: warp = head; lane handles query rows (lane, lane+32) ----
    {
        const int h = tid >> 5;
        const int lane = tid & 31;
        float qa[DK], qb[DK], aa[DK] = {}, ab[DK] = {};
        #pragma unroll
        for (int i = 0; i < DK; ++i) {
            qa[i] = sq[lane * PAD + h * DK + i];
            qb[i] = sq[(lane + 32) * PAD + h * DK + i];
        }
        float ma = -1e30f, mb = -1e30f, sa = 0.f, sb = 0.f;
        for (int s = 0; s < SS; ++s) {
            float da = 0.f, db = 0.f;
            #pragma unroll
            for (int i = 0; i < DK; ++i) {
                float kk = sk[s * PAD + h * DK + i];
                da += qa[i] * kk;
                db += qb[i] * kk;
            }
            float mna = fmaxf(ma, da), mnb = fmaxf(mb, db);
            float ca = __expf(ma - mna), pa = __expf(da - mna);
            float cb = __expf(mb - mnb), pb = __expf(db - mnb);
            sa = sa * ca + pa;
            sb = sb * cb + pb;
            ma = mna; mb = mnb;
            #pragma unroll
            for (int i = 0; i < DK; ++i) {
                float vv = sv[s * PAD + h * DK + i];
                aa[i] = aa[i] * ca + pa * vv;
                ab[i] = ab[i] * cb + pb * vv;
            }
        }
        float ra = 1.f / sa, rb = 1.f / sb;
        #pragma unroll
        for (int i = 0; i < DK; ++i) {
            sXt[(h * DK + i) * PAD + lane] = aa[i] * ra;
            sXt[(h * DK + i) * PAD + lane + 32] = ab[i] * rb;
        }
    }
    __syncthreads();

    // ---- output projection ----
    {
        float acc[4][4] = {};
        mm16(sXt, sWt, tx, ty, acc);
        #pragma unroll
        for (int i = 0; i < 4; ++i) {
            int l = 4 * ty + i;
            float4 o = make_float4(acc[i][0] + bo[4 * tx + 0],
                                   acc[i][1] + bo[4 * tx + 1],
                                   acc[i][2] + bo[4 * tx + 2],
                                   acc[i][3] + bo[4 * tx + 3]);
            *(float4*)(out + ((long)(b * LL + l) * NN + n) * DD + 4 * tx) = o;
        }
    }
}

// ---------------- launch ----------------
extern "C" void kernel_launch(void* const* d_in, const int* in_sizes, int n_in,
                              void* d_out, int out_size) {
    const float* queries = (const float*)d_in[0];
    const float* keys    = (const float*)d_in[1];
    const float* values  = (const float*)d_in[2];
    const float* support = (const float*)d_in[3];
    const float* Wq = (const float*)d_in[4];
    const float* bq = (const float*)d_in[5];
    const float* Wk = (const float*)d_in[6];
    const float* bk = (const float*)d_in[7];
    const float* Wv = (const float*)d_in[8];
    const float* bv = (const float*)d_in[9];
    const float* Wo = (const float*)d_in[10];
    const float* bo = (const float*)d_in[11];
    const float* Wg1 = (const float*)d_in[12];
    const float* bg1 = (const float*)d_in[13];
    const float* Wg2 = (const float*)d_in[14];
    const float* bg2 = (const float*)d_in[15];
    float* out = (float*)d_out;

    cudaFuncSetAttribute(gemm_mma_kernel, cudaFuncAttributeMaxDynamicSharedMemorySize, GEMM_SMEM);
    cudaFuncSetAttribute(attn_kernel, cudaFuncAttributeMaxDynamicSharedMemorySize,
                         5 * 64 * PAD * (int)sizeof(float));

    transpose_kernel<<<(NN * NN + 255) / 256, 256>>>(support);
    pack_kernel<<<dim3(24, 2, 256), 256>>>(keys, values);
    prep_w_kernel<<<2, 256>>>(Wk, bk, Wg1, bg1, Wv, bv, Wg2, bg2);

    // A2 = At @ support   (N = 768 -> 6 ntiles, 6 mtiles)
    gemm_mma_kernel<<<dim3(36, 1), 256, GEMM_SMEM>>>(support, 0);
    // diffusion: K1, K2, V1, V2   (N = 16384 -> 128 ntiles, 6 mtiles)
    gemm_mma_kernel<<<dim3(768, 4), 256, GEMM_SMEM>>>(nullptr, 1);

    const int smem = 5 * 64 * PAD * (int)sizeof(float);  // 87,040 B
    attn_kernel<<<dim3(NN, BB), 256, smem>>>(queries, keys, values, Wq, bq, Wo, bo, out);
}

// round 5
// speedup vs baseline: 2.5331x; 1.1737x over previous
#include <cuda_runtime.h>
#include <cuda_bf16.h>
#include <cstdint>

// Problem constants
#define BB 4
#define LL 64
#define SS 64
#define NN 768
#define DD 64
#define HH 8
#define DK 8
#define CING 192
#define JJ 16384   // B*S*D = 256*64
#define PAD 68

// ---------------- scratch (__device__ globals) ----------------
__device__ __nv_bfloat16 g_AtH[NN * 1536];   // cols 0..767: At ; cols 768..1535: A2 (written by mode0)
__device__ __nv_bfloat16 g_AtL[NN * 1536];
__device__ __nv_bfloat16 g_SuH[NN * NN];     // support hi/lo (B operand of mode0)
__device__ __nv_bfloat16 g_SuL[NN * NN];
__device__ __nv_bfloat16 g_PkH[JJ * 1536];   // row j=bs*64+e: cols 0..767 = P1k^T, 768.. = P2k^T
__device__ __nv_bfloat16 g_PkL[JJ * 1536];
__device__ __nv_bfloat16 g_PvH[JJ * 1536];
__device__ __nv_bfloat16 g_PvL[JJ * 1536];
__device__ float g_Kf[NN * JJ];              // final projected K: [n][bs*64+e]
__device__ float g_Vf[NN * JJ];
__device__ float g_Qp[256 * NN * DD];        // projected+scaled Q: [(b*64+l)][n][e]
__device__ float g_WkG1[DD * CING];
__device__ float g_WvG2[DD * CING];
__device__ float g_bk2[DD];
__device__ float g_bv2[DD];

// ================= PTX helpers (vanilla compute_103) =================
__device__ __forceinline__ uint32_t smem_u32_of(const void* p) {
    uint32_t a;
    asm("{ .reg .u64 t; cvta.to.shared.u64 t, %1; cvt.u32.u64 %0, t; }" : "=r"(a) : "l"(p));
    return a;
}
__device__ __forceinline__ void ldm_x4(uint32_t& r0, uint32_t& r1, uint32_t& r2, uint32_t& r3,
                                       uint32_t addr) {
    asm volatile("ldmatrix.sync.aligned.m8n8.x4.shared.b16 {%0,%1,%2,%3}, [%4];"
                 : "=r"(r0), "=r"(r1), "=r"(r2), "=r"(r3) : "r"(addr));
}
__device__ __forceinline__ void mma_bf16(float* c, const uint32_t* a, const uint32_t* b) {
    asm volatile("mma.sync.aligned.m16n8k16.row.col.f32.bf16.bf16.f32 "
                 "{%0,%1,%2,%3}, {%4,%5,%6,%7}, {%8,%9}, {%0,%1,%2,%3};"
                 : "+f"(c[0]), "+f"(c[1]), "+f"(c[2]), "+f"(c[3])
                 : "r"(a[0]), "r"(a[1]), "r"(a[2]), "r"(a[3]), "r"(b[0]), "r"(b[1]));
}
__device__ __forceinline__ void cp16(uint32_t saddr, const void* g) {
    asm volatile("cp.async.cg.shared.global [%0], [%1], 16;" :: "r"(saddr), "l"(g));
}
#define CP_COMMIT() asm volatile("cp.async.commit_group;")
#define CP_WAIT0()  asm volatile("cp.async.wait_group 0;")

__device__ __forceinline__ void split4(float4 f, uint2& h, uint2& l) {
    __nv_bfloat162 h01 = __floats2bfloat162_rn(f.x, f.y);
    __nv_bfloat162 h23 = __floats2bfloat162_rn(f.z, f.w);
    float2 g01 = __bfloat1622float2(h01), g23 = __bfloat1622float2(h23);
    __nv_bfloat162 l01 = __floats2bfloat162_rn(f.x - g01.x, f.y - g01.y);
    __nv_bfloat162 l23 = __floats2bfloat162_rn(f.z - g23.x, f.w - g23.y);
    h = make_uint2(*(uint32_t*)&h01, *(uint32_t*)&h23);
    l = make_uint2(*(uint32_t*)&l01, *(uint32_t*)&l23);
}
__device__ __forceinline__ void split2_store(float c0, float c1,
                                             __nv_bfloat16* ph, __nv_bfloat16* pl) {
    __nv_bfloat162 h = __floats2bfloat162_rn(c0, c1);
    float2 hf = __bfloat1622float2(h);
    __nv_bfloat162 l = __floats2bfloat162_rn(c0 - hf.x, c1 - hf.y);
    *(uint32_t*)ph = *(uint32_t*)&h;
    *(uint32_t*)pl = *(uint32_t*)&l;
}

// ---------------- prep: At + support -> bf16 hi/lo ----------------
__global__ void prep_split_kernel(const float* __restrict__ a) {
    int idx = blockIdx.x * 256 + threadIdx.x;
    if (idx < NN * NN) {
        int n = idx / NN, v = idx - n * NN;
        float tv = a[v * NN + n];                    // At[n][v]
        __nv_bfloat16 h = __float2bfloat16(tv);
        g_AtH[n * 1536 + v] = h;
        g_AtL[n * 1536 + v] = __float2bfloat16(tv - __bfloat162float(h));
        float sv = a[idx];                           // support row-major
        h = __float2bfloat16(sv);
        g_SuH[idx] = h;
        g_SuL[idx] = __float2bfloat16(sv - __bfloat162float(h));
    }
}

// ---------------- prep: fold MLP weight into K/V projections ----------------
__global__ void prep_w_kernel(const float* __restrict__ Wk, const float* __restrict__ bk,
                              const float* __restrict__ Wg1, const float* __restrict__ bg1,
                              const float* __restrict__ Wv, const float* __restrict__ bv,
                              const float* __restrict__ Wg2, const float* __restrict__ bg2) {
    const float* W1 = blockIdx.x ? Wv : Wk;
    const float* Wg = blockIdx.x ? Wg2 : Wg1;
    const float* bg = blockIdx.x ? bg2 : bg1;
    const float* bb = blockIdx.x ? bv : bk;
    float* WG = blockIdx.x ? g_WvG2 : g_WkG1;
    float* b2 = blockIdx.x ? g_bv2 : g_bk2;

    __shared__ float sW[DD * DD];
    for (int i = threadIdx.x; i < DD * DD; i += 256) sW[i] = W1[i];
    __syncthreads();

    for (int idx = threadIdx.x; idx < DD * CING; idx += 256) {
        int e = idx / CING;
        int c = idx - e * CING;
        float s = 0.f;
        #pragma unroll 8
        for (int o = 0; o < DD; ++o) s += sW[e * DD + o] * Wg[o * CING + c];
        WG[idx] = s;
    }
    if (threadIdx.x < DD) {
        float s = 0.f;
        for (int o = 0; o < DD; ++o) s += sW[threadIdx.x * DD + o] * bg[o];
        b2[threadIdx.x] = s + bb[threadIdx.x];
    }
}

// =========================================================================
// proj kernel: per (ntile, bs, path) with X tile 128 rows x 64 ch.
//  pass a: C1[n][e] = X @ W0^T (+bias [,*scale]) -> output buffer (P0 term)
//  pass b (K/V only): C2[e'][n] = Wstack(W1;W2) @ X^T -> split bf16 into P buffers
// =========================================================================
#define PJ_XH 0
#define PJ_XL 18432
#define PJ_WH 36864
#define PJ_WL 64512
#define PROJ_SMEM 92160

__global__ __launch_bounds__(256) void proj_kernel(const float* __restrict__ keys,
                                                   const float* __restrict__ values,
                                                   const float* __restrict__ queries,
                                                   const float* __restrict__ Wq,
                                                   const float* __restrict__ bq) {
    extern __shared__ char smem[];
    const uint32_t smem_b = smem_u32_of(smem);
    const int tid = threadIdx.x, wid = tid >> 5, lane = tid & 31;
    const int warp_m = wid & 1, warp_n = wid >> 1;
    const int ntile = blockIdx.x;     // 0..5
    const int bs = blockIdx.y;        // 0..255
    const int path = blockIdx.z;      // 0 K, 1 V, 2 Q
    const int n0 = ntile * 128;

    const float* X = (path == 0) ? keys : (path == 1) ? values : queries;
    X += (long)bs * NN * DD;
    const float* WG = (path == 0) ? g_WkG1 : g_WvG2;

    // stage X (128 x 64) -> hi/lo bf16, 144B rows
    #pragma unroll
    for (int i = 0; i < 8; ++i) {
        int idx = tid + (i << 8);
        int r = idx >> 4, c4 = (idx & 15) << 2;
        float4 f = *(const float4*)(X + (long)(n0 + r) * DD + c4);
        uint2 h, l;
        split4(f, h, l);
        *(uint2*)(smem + PJ_XH + r * 144 + c4 * 2) = h;
        *(uint2*)(smem + PJ_XL + r * 144 + c4 * 2) = l;
    }
    // stage W (192 rows x 64) -> hi/lo
    #pragma unroll
    for (int i = 0; i < 12; ++i) {
        int idx = tid + (i << 8);
        int r = idx >> 4, c4 = (idx & 15) << 2;
        float4 f;
        if (path == 2) {
            f = (r < 64) ? *(const float4*)(Wq + r * DD + c4) : make_float4(0.f, 0.f, 0.f, 0.f);
        } else {
            int er = (r < 64) ? r : (r < 128 ? r - 64 : r - 128);
            int co = (r < 64) ? 0 : (r < 128 ? 64 : 128);
            f = *(const float4*)(WG + er * CING + co + c4);
        }
        uint2 h, l;
        split4(f, h, l);
        *(uint2*)(smem + PJ_WH + r * 144 + c4 * 2) = h;
        *(uint2*)(smem + PJ_WL + r * 144 + c4 * 2) = l;
    }
    __syncthreads();

    const int a_r = lane & 15, a_c = (lane >> 4) << 3;
    const int b_m = lane >> 3;
    const int b_n = (lane & 7) + ((b_m >> 1) << 3);
    const int b_k = (b_m & 1) << 3;
    const int g = lane >> 2, t = lane & 3;

    // ---- pass a: C1[n 128][e 64] = X @ W0^T ----
    {
        float acc[4][2][4] = {};
        const uint32_t abase = smem_b + (warp_m * 64 + a_r) * 144 + a_c * 2;
        const uint32_t bbase = smem_b + (warp_n * 16 + b_n) * 144 + b_k * 2;
        #pragma unroll
        for (int kc = 0; kc < 4; ++kc) {
            uint32_t kO = kc * 32;
            uint32_t ah[4][4], al_[4][4], bh[2][2], bl_[2][2];
            #pragma unroll
            for (int mi = 0; mi < 4; ++mi) {
                uint32_t ad = abase + mi * 2304 + kO;
                ldm_x4(ah[mi][0], ah[mi][1], ah[mi][2], ah[mi][3], ad + PJ_XH);
                ldm_x4(al_[mi][0], al_[mi][1], al_[mi][2], al_[mi][3], ad + PJ_XL);
            }
            ldm_x4(bh[0][0], bh[0][1], bh[1][0], bh[1][1], bbase + PJ_WH + kO);
            ldm_x4(bl_[0][0], bl_[0][1], bl_[1][0], bl_[1][1], bbase + PJ_WL + kO);
            #pragma unroll
            for (int mi = 0; mi < 4; ++mi)
                #pragma unroll
                for (int nj = 0; nj < 2; ++nj) {
                    mma_bf16(acc[mi][nj], ah[mi], bh[nj]);
                    mma_bf16(acc[mi][nj], ah[mi], bl_[nj]);
                    mma_bf16(acc[mi][nj], al_[mi], bh[nj]);
                }
        }
        #pragma unroll
        for (int mi = 0; mi < 4; ++mi)
            #pragma unroll
            for (int nj = 0; nj < 2; ++nj) {
                int nr = n0 + warp_m * 64 + mi * 16 + g;
                int e = warp_n * 16 + nj * 8 + t * 2;
                if (path == 2) {
                    const float sc = 0.35355339059327373f;
                    *(float2*)(g_Qp + ((long)bs * NN + nr) * DD + e) =
                        make_float2(acc[mi][nj][0] * sc + bq[e] * sc,
                                    acc[mi][nj][1] * sc + bq[e + 1] * sc);
                    *(float2*)(g_Qp + ((long)bs * NN + nr + 8) * DD + e) =
                        make_float2(acc[mi][nj][2] * sc + bq[e] * sc,
                                    acc[mi][nj][3] * sc + bq[e + 1] * sc);
                } else {
                    float* Cout = path ? g_Vf : g_Kf;
                    const float* bias = path ? g_bv2 : g_bk2;
                    *(float2*)(Cout + (long)nr * JJ + bs * 64 + e) =
                        make_float2(acc[mi][nj][0] + bias[e], acc[mi][nj][1] + bias[e + 1]);
                    *(float2*)(Cout + (long)(nr + 8) * JJ + bs * 64 + e) =
                        make_float2(acc[mi][nj][2] + bias[e], acc[mi][nj][3] + bias[e + 1]);
                }
            }
    }

    // ---- pass b: C2[e' 128][n 128] = Wstack @ X^T -> split store ----
    if (path < 2) {
        float acc[4][4][4] = {};
        const uint32_t abase = smem_b + (64 + warp_m * 64 + a_r) * 144 + a_c * 2;
        const uint32_t bbase = smem_b + (warp_n * 32 + b_n) * 144 + b_k * 2;
        #pragma unroll
        for (int kc = 0; kc < 4; ++kc) {
            uint32_t kO = kc * 32;
            uint32_t ah[4][4], al_[4][4], bh[4][2], bl_[4][2];
            #pragma unroll
            for (int mi = 0; mi < 4; ++mi) {
                uint32_t ad = abase + mi * 2304 + kO;
                ldm_x4(ah[mi][0], ah[mi][1], ah[mi][2], ah[mi][3], ad + PJ_WH);
                ldm_x4(al_[mi][0], al_[mi][1], al_[mi][2], al_[mi][3], ad + PJ_WL);
            }
            #pragma unroll
            for (int p = 0; p < 2; ++p) {
                uint32_t bd = bbase + p * 2304 + kO;
                ldm_x4(bh[2 * p][0], bh[2 * p][1], bh[2 * p + 1][0], bh[2 * p + 1][1], bd + PJ_XH);
                ldm_x4(bl_[2 * p][0], bl_[2 * p][1], bl_[2 * p + 1][0], bl_[2 * p + 1][1], bd + PJ_XL);
            }
            #pragma unroll
            for (int mi = 0; mi < 4; ++mi)
                #pragma unroll
                for (int nj = 0; nj < 4; ++nj) {
                    mma_bf16(acc[mi][nj], ah[mi], bh[nj]);
                    mma_bf16(acc[mi][nj], ah[mi], bl_[nj]);
                    mma_bf16(acc[mi][nj], al_[mi], bh[nj]);
                }
        }
        __nv_bfloat16* PH = path ? g_PvH : g_PkH;
        __nv_bfloat16* PL = path ? g_PvL : g_PkL;
        #pragma unroll
        for (int mi = 0; mi < 4; ++mi)
            #pragma unroll
            for (int nj = 0; nj < 4; ++nj) {
                int ep = warp_m * 64 + mi * 16 + g;
                int nl = n0 + warp_n * 32 + nj * 8 + t * 2;
                long row0 = (long)bs * 64 + (ep & 63);
                long col = (long)(ep >> 6) * 768 + nl;
                split2_store(acc[mi][nj][0], acc[mi][nj][1], PH + row0 * 1536 + col,
                             PL + row0 * 1536 + col);
                long row1 = (long)bs * 64 + ((ep + 8) & 63);
                split2_store(acc[mi][nj][2], acc[mi][nj][3], PH + row1 * 1536 + col,
                             PL + row1 * 1536 + col);
            }
    }
}

// =========================================================================
// big GEMM (cp.async, pre-split bf16 inputs), tile 128x128, Kc=64
// mode 0: A2 = At @ support : 36 CTAs, k=768, epilogue split-> g_AtH/L cols 768+
// mode 1: C += [At|A2] @ [P1;P2] : grid (768, 2), k=1536, fp32 accumulate epilogue
// =========================================================================
#define O_AH 0
#define O_AL 18432
#define O_BH 36864
#define O_BL 55296
#define STAGEB 73728
#define GEMM_SMEM (2 * STAGEB)

__global__ __launch_bounds__(256, 1) void gemm_big_kernel(int mode) {
    extern __shared__ char smem[];
    const uint32_t smem_b = smem_u32_of(smem);
    const int tid = threadIdx.x, wid = tid >> 5, lane = tid & 31;
    const int warp_m = wid & 1, warp_n = wid >> 1;
    const int mtile = blockIdx.x % 6, ntile = blockIdx.x / 6;
    const int m0 = mtile * 128, j0 = ntile * 128;

    const __nv_bfloat16* Ah = g_AtH;
    const __nv_bfloat16* Al = g_AtL;
    const __nv_bfloat16 *Bh, *Bl;
    long sB;
    int ktiles;
    float* Cacc = nullptr;
    if (mode == 0) {
        Bh = g_SuH; Bl = g_SuL; sB = NN; ktiles = 12;
    } else {
        int p = blockIdx.y;
        Bh = p ? g_PvH : g_PkH;
        Bl = p ? g_PvL : g_PkL;
        sB = 1536; ktiles = 24;
        Cacc = p ? g_Vf : g_Kf;
    }
    const long sA = 1536;

    #define ISSUE_STAGE(kt)                                                      \
        {                                                                        \
            uint32_t st = smem_b + ((kt) & 1) * STAGEB;                          \
            long ko = (long)(kt) * 64;                                           \
            _Pragma("unroll")                                                    \
            for (int i = 0; i < 4; ++i) {                                        \
                int ch = tid + (i << 8);                                         \
                int r = ch >> 3, c = ch & 7;                                     \
                uint32_t so = st + r * 144 + c * 16;                             \
                cp16(so + O_AH, Ah + (long)(m0 + r) * sA + ko + c * 8);          \
                cp16(so + O_AL, Al + (long)(m0 + r) * sA + ko + c * 8);          \
                cp16(so + O_BH, Bh + (long)(j0 + r) * sB + ko + c * 8);          \
                cp16(so + O_BL, Bl + (long)(j0 + r) * sB + ko + c * 8);          \
            }                                                                    \
            CP_COMMIT();                                                         \
        }

    float acc[4][4][4] = {};

    const int a_r = lane & 15, a_c = (lane >> 4) << 3;
    const int b_m = lane >> 3;
    const int b_n = (lane & 7) + ((b_m >> 1) << 3);
    const int b_k = (b_m & 1) << 3;
    const uint32_t a_base = (uint32_t)((warp_m * 64 + a_r) * 144 + a_c * 2);
    const uint32_t b_base = (uint32_t)((warp_n * 32 + b_n) * 144 + b_k * 2);

    ISSUE_STAGE(0);

    for (int kt = 0; kt < ktiles; ++kt) {
        CP_WAIT0();
        __syncthreads();
        if (kt + 1 < ktiles) ISSUE_STAGE(kt + 1);

        const uint32_t sbase = smem_b + (kt & 1) * STAGEB;
        #pragma unroll
        for (int kc = 0; kc < 4; ++kc) {
            const uint32_t kO = kc * 32;
            uint32_t ah[4][4], al_[4][4], bh[4][2], bl_[4][2];
            #pragma unroll
            for (int mi = 0; mi < 4; ++mi) {
                uint32_t ad = sbase + a_base + mi * 2304 + kO;
                ldm_x4(ah[mi][0], ah[mi][1], ah[mi][2], ah[mi][3], ad + O_AH);
                ldm_x4(al_[mi][0], al_[mi][1], al_[mi][2], al_[mi][3], ad + O_AL);
            }
            #pragma unroll
            for (int p = 0; p < 2; ++p) {
                uint32_t bd = sbase + b_base + p * 2304 + kO;
                ldm_x4(bh[2 * p][0], bh[2 * p][1], bh[2 * p + 1][0], bh[2 * p + 1][1], bd + O_BH);
                ldm_x4(bl_[2 * p][0], bl_[2 * p][1], bl_[2 * p + 1][0], bl_[2 * p + 1][1], bd + O_BL);
            }
            #pragma unroll
            for (int mi = 0; mi < 4; ++mi)
                #pragma unroll
                for (int nj = 0; nj < 4; ++nj) {
                    mma_bf16(acc[mi][nj], ah[mi], bh[nj]);
                    mma_bf16(acc[mi][nj], ah[mi], bl_[nj]);
                    mma_bf16(acc[mi][nj], al_[mi], bh[nj]);
                }
        }
        __syncthreads();
    }

    // epilogue
    {
        const int g = lane >> 2, t = lane & 3;
        if (mode == 0) {
            #pragma unroll
            for (int mi = 0; mi < 4; ++mi) {
                int m = m0 + warp_m * 64 + mi * 16 + g;
                #pragma unroll
                for (int nj = 0; nj < 4; ++nj) {
                    int col = 768 + j0 + warp_n * 32 + nj * 8 + t * 2;
                    split2_store(acc[mi][nj][0], acc[mi][nj][1],
                                 g_AtH + (long)m * 1536 + col, g_AtL + (long)m * 1536 + col);
                    split2_store(acc[mi][nj][2], acc[mi][nj][3],
                                 g_AtH + (long)(m + 8) * 1536 + col, g_AtL + (long)(m + 8) * 1536 + col);
                }
            }
        } else {
            #pragma unroll
            for (int mi = 0; mi < 4; ++mi) {
                int m = m0 + warp_m * 64 + mi * 16 + g;
                #pragma unroll
                for (int nj = 0; nj < 4; ++nj) {
                    int col = j0 + warp_n * 32 + nj * 8 + t * 2;
                    float2 o0 = *(float2*)(Cacc + (long)m * JJ + col);
                    *(float2*)(Cacc + (long)m * JJ + col) =
                        make_float2(o0.x + acc[mi][nj][0], o0.y + acc[mi][nj][1]);
                    float2 o1 = *(float2*)(Cacc + (long)(m + 8) * JJ + col);
                    *(float2*)(Cacc + (long)(m + 8) * JJ + col) =
                        make_float2(o1.x + acc[mi][nj][2], o1.y + acc[mi][nj][3]);
                }
            }
        }
    }
    #undef ISSUE_STAGE
}

// ---------------- attn helpers ----------------
__device__ __forceinline__ void mm16(const float* __restrict__ sXt, const float* __restrict__ sWt,
                                     int tx, int ty, float acc[4][4]) {
    #pragma unroll 8
    for (int d = 0; d < 64; ++d) {
        float4 xv = *(const float4*)(sXt + d * PAD + ty * 4);
        float4 wv = *(const float4*)(sWt + d * PAD + tx * 4);
        float xs[4] = {xv.x, xv.y, xv.z, xv.w};
        float ws[4] = {wv.x, wv.y, wv.z, wv.w};
        #pragma unroll
        for (int i = 0; i < 4; ++i)
            #pragma unroll
            for (int j = 0; j < 4; ++j)
                acc[i][j] += xs[i] * ws[j];
    }
}
__device__ __forceinline__ void stage_xt(const float* __restrict__ src, long rowstride,
                                         float* __restrict__ dst, int tid) {
    #pragma unroll
    for (int it = 0; it < 4; ++it) {
        int idx = tid + it * 256;
        int r = idx >> 4;
        int c4 = (idx & 15) << 2;
        float4 f = *(const float4*)(src + (long)r * rowstride + c4);
        dst[(c4 + 0) * PAD + r] = f.x;
        dst[(c4 + 1) * PAD + r] = f.y;
        dst[(c4 + 2) * PAD + r] = f.z;
        dst[(c4 + 3) * PAD + r] = f.w;
    }
}

// ---------------- attention + output projection ----------------
__global__ __launch_bounds__(256) void attn_kernel(const float* __restrict__ Wo,
                                                   const float* __restrict__ bo,
                                                   float* __restrict__ out) {
    extern __shared__ float sm[];
    float* sXt = sm;                 // attn-out^T staging
    float* sWt = sm + 64 * PAD;
    float* sq = sm + 2 * 64 * PAD;
    float* sk = sm + 3 * 64 * PAD;
    float* sv = sm + 4 * 64 * PAD;

    const int n = blockIdx.x;
    const int b = blockIdx.y;
    const int tid = threadIdx.x;
    const int tx = tid & 15, ty = tid >> 4;

    // stage precomputed q/k/v
    #pragma unroll
    for (int i = 0; i < 4; ++i) {
        int idx = tid + (i << 8);
        int r = idx >> 4, c4 = (idx & 15) << 2;
        *(float4*)&sq[r * PAD + c4] = *(const float4*)(g_Qp + ((long)(b * 64 + r) * NN + n) * DD + c4);
        *(float4*)&sk[r * PAD + c4] = *(const float4*)(g_Kf + (long)n * JJ + b * 4096 + r * 64 + c4);
        *(float4*)&sv[r * PAD + c4] = *(const float4*)(g_Vf + (long)n * JJ + b * 4096 + r * 64 + c4);
    }
    stage_xt(Wo, DD, sWt, tid);
    __syncthreads();

    // attention: warp = head; lane handles query rows (lane, lane+32)
    {
        const int h = tid >> 5;
        const int lane = tid & 31;
        float qa[DK], qb[DK], aa[DK] = {}, ab[DK] = {};
        #pragma unroll
        for (int i = 0; i < DK; ++i) {
            qa[i] = sq[lane * PAD + h * DK + i];
            qb[i] = sq[(lane + 32) * PAD + h * DK + i];
        }
        float ma = -1e30f, mb = -1e30f, sa = 0.f, sb = 0.f;
        for (int s = 0; s < SS; ++s) {
            float da = 0.f, db = 0.f;
            #pragma unroll
            for (int i = 0; i < DK; ++i) {
                float kk = sk[s * PAD + h * DK + i];
                da += qa[i] * kk;
                db += qb[i] * kk;
            }
            float mna = fmaxf(ma, da), mnb = fmaxf(mb, db);
            float ca = __expf(ma - mna), pa = __expf(da - mna);
            float cb = __expf(mb - mnb), pb = __expf(db - mnb);
            sa = sa * ca + pa;
            sb = sb * cb + pb;
            ma = mna; mb = mnb;
            #pragma unroll
            for (int i = 0; i < DK; ++i) {
                float vv = sv[s * PAD + h * DK + i];
                aa[i] = aa[i] * ca + pa * vv;
                ab[i] = ab[i] * cb + pb * vv;
            }
        }
        float ra = 1.f / sa, rb = 1.f / sb;
        #pragma unroll
        for (int i = 0; i < DK; ++i) {
            sXt[(h * DK + i) * PAD + lane] = aa[i] * ra;
            sXt[(h * DK + i) * PAD + lane + 32] = ab[i] * rb;
        }
    }
    __syncthreads();

    // output projection
    {
        float acc[4][4] = {};
        mm16(sXt, sWt, tx, ty, acc);
        #pragma unroll
        for (int i = 0; i < 4; ++i) {
            int l = 4 * ty + i;
            float4 o = make_float4(acc[i][0] + bo[4 * tx + 0],
                                   acc[i][1] + bo[4 * tx + 1],
                                   acc[i][2] + bo[4 * tx + 2],
                                   acc[i][3] + bo[4 * tx + 3]);
            *(float4*)(out + ((long)(b * LL + l) * NN + n) * DD + 4 * tx) = o;
        }
    }
}

// ---------------- launch ----------------
extern "C" void kernel_launch(void* const* d_in, const int* in_sizes, int n_in,
                              void* d_out, int out_size) {
    const float* queries = (const float*)d_in[0];
    const float* keys    = (const float*)d_in[1];
    const float* values  = (const float*)d_in[2];
    const float* support = (const float*)d_in[3];
    const float* Wq = (const float*)d_in[4];
    const float* bq = (const float*)d_in[5];
    const float* Wk = (const float*)d_in[6];
    const float* bk = (const float*)d_in[7];
    const float* Wv = (const float*)d_in[8];
    const float* bv = (const float*)d_in[9];
    const float* Wo = (const float*)d_in[10];
    const float* bo = (const float*)d_in[11];
    const float* Wg1 = (const float*)d_in[12];
    const float* bg1 = (const float*)d_in[13];
    const float* Wg2 = (const float*)d_in[14];
    const float* bg2 = (const float*)d_in[15];
    float* out = (float*)d_out;

    cudaFuncSetAttribute(gemm_big_kernel, cudaFuncAttributeMaxDynamicSharedMemorySize, GEMM_SMEM);
    cudaFuncSetAttribute(proj_kernel, cudaFuncAttributeMaxDynamicSharedMemorySize, PROJ_SMEM);
    cudaFuncSetAttribute(attn_kernel, cudaFuncAttributeMaxDynamicSharedMemorySize,
                         5 * 64 * PAD * (int)sizeof(float));

    prep_split_kernel<<<2304, 256>>>(support);
    prep_w_kernel<<<2, 256>>>(Wk, bk, Wg1, bg1, Wv, bv, Wg2, bg2);

    // A2 = At @ support (split-stored into g_AtH/L cols 768+)
    gemm_big_kernel<<<dim3(36, 1), 256, GEMM_SMEM>>>(0);
    // projections: P0 terms (+bias) into g_Kf/g_Vf/g_Qp, P1/P2 split into P buffers
    proj_kernel<<<dim3(6, 256, 3), 256, PROJ_SMEM>>>(keys, values, queries, Wq, bq);
    // diffusion: C += [At|A2] @ [P1;P2]   (paths K, V)
    gemm_big_kernel<<<dim3(768, 2), 256, GEMM_SMEM>>>(1);

    const int smem = 5 * 64 * PAD * (int)sizeof(float);
    attn_kernel<<<dim3(NN, BB), 256, smem>>>(Wo, bo, out);
}